// round 1
// baseline (speedup 1.0000x reference)
#include <cuda_runtime.h>
#include <math.h>

#define N_NODES 50000
#define N_EDGES 800000
#define EMB     100
#define NTHREADS 128

// ---- static scratch (allocation-free rule: __device__ globals) ----
__device__ int   g_rowoff[N_NODES + 1];   // CSR row offsets
__device__ int   g_cursor[N_NODES];       // histogram counts, then scatter cursors
__device__ int   g_perm[N_EDGES];         // edge ids grouped by dest row
__device__ float g_x1[N_NODES * EMB];
__device__ float g_x2[N_NODES * EMB];
__device__ float g_x3[N_NODES * EMB];

// ---------------- CSR build ----------------
__global__ void zero_counts_kernel() {
    int i = blockIdx.x * blockDim.x + threadIdx.x;
    if (i < N_NODES) g_cursor[i] = 0;
}

__global__ void hist_kernel(const int* __restrict__ row) {
    int e = blockIdx.x * blockDim.x + threadIdx.x;
    if (e < N_EDGES) atomicAdd(&g_cursor[row[e]], 1);
}

// single-block exclusive scan over 50000 counts -> rowoff; cursor <- start offsets
__global__ void scan_kernel() {
    __shared__ int sh[1024];
    const int t = threadIdx.x;
    int carry = 0;
    if (t == 0) g_rowoff[0] = 0;
    for (int base = 0; base < N_NODES; base += 1024) {
        int i = base + t;
        int v = (i < N_NODES) ? g_cursor[i] : 0;
        sh[t] = v;
        __syncthreads();
        // Hillis-Steele inclusive scan
        #pragma unroll
        for (int off = 1; off < 1024; off <<= 1) {
            int x = (t >= off) ? sh[t - off] : 0;
            __syncthreads();
            sh[t] += x;
            __syncthreads();
        }
        int incl = sh[t];
        if (i < N_NODES) {
            g_rowoff[i + 1] = carry + incl;
            g_cursor[i]     = carry + incl - v;   // start offset (cursor)
        }
        int total = sh[1023];
        __syncthreads();   // protect sh before next chunk overwrite
        carry += total;
    }
}

__global__ void scatter_kernel(const int* __restrict__ row) {
    int e = blockIdx.x * blockDim.x + threadIdx.x;
    if (e < N_EDGES) {
        int pos = atomicAdd(&g_cursor[row[e]], 1);
        g_perm[pos] = e;
    }
}

// ---------------- SpMM: y[r,:] = sum_{e in row r} val[e] * x[col[e],:] ----------------
__global__ void __launch_bounds__(NTHREADS) spmm_kernel(
    const float* __restrict__ x, float* __restrict__ y,
    const int* __restrict__ col, const float* __restrict__ val) {
    const int r = blockIdx.x;
    const int t = threadIdx.x;
    const int s = g_rowoff[r];
    const int e = g_rowoff[r + 1];

    __shared__ int   scol[NTHREADS];   // col * EMB, precomputed
    __shared__ float sval[NTHREADS];

    float acc = 0.0f;
    for (int base = s; base < e; base += NTHREADS) {
        int n = e - base;
        if (n > NTHREADS) n = NTHREADS;
        if (t < n) {
            int ed  = g_perm[base + t];
            scol[t] = col[ed] * EMB;
            sval[t] = val[ed];
        }
        __syncthreads();
        if (t < EMB) {
            int k = 0;
            for (; k + 3 < n; k += 4) {
                float a0 = sval[k + 0] * __ldg(&x[scol[k + 0] + t]);
                float a1 = sval[k + 1] * __ldg(&x[scol[k + 1] + t]);
                float a2 = sval[k + 2] * __ldg(&x[scol[k + 2] + t]);
                float a3 = sval[k + 3] * __ldg(&x[scol[k + 3] + t]);
                acc += (a0 + a1) + (a2 + a3);
            }
            for (; k < n; k++)
                acc += sval[k] * __ldg(&x[scol[k] + t]);
        }
        __syncthreads();
    }
    if (t < EMB) y[r * EMB + t] = acc;
}

// ---------------- finalize: out = sum_l a[l] * normalize(x_l) ----------------
__global__ void __launch_bounds__(NTHREADS) finalize_kernel(
    const float* __restrict__ emb, const float* __restrict__ a,
    float* __restrict__ out) {
    const int r = blockIdx.x;
    const int t = threadIdx.x;

    float v[4];
    const float* x0 = emb  + (size_t)r * EMB;
    const float* x1 = g_x1 + (size_t)r * EMB;
    const float* x2 = g_x2 + (size_t)r * EMB;
    const float* x3 = g_x3 + (size_t)r * EMB;
    v[0] = (t < EMB) ? x0[t] : 0.0f;
    v[1] = (t < EMB) ? x1[t] : 0.0f;
    v[2] = (t < EMB) ? x2[t] : 0.0f;
    v[3] = (t < EMB) ? x3[t] : 0.0f;

    float sq[4];
    #pragma unroll
    for (int l = 0; l < 4; l++) sq[l] = v[l] * v[l];

    // warp reduce (4 values)
    #pragma unroll
    for (int off = 16; off > 0; off >>= 1) {
        #pragma unroll
        for (int l = 0; l < 4; l++)
            sq[l] += __shfl_xor_sync(0xFFFFFFFFu, sq[l], off);
    }

    __shared__ float wsum[4][4];   // [warp][layer]
    const int warp = t >> 5, lane = t & 31;
    if (lane == 0) {
        #pragma unroll
        for (int l = 0; l < 4; l++) wsum[warp][l] = sq[l];
    }
    __syncthreads();

    if (t < EMB) {
        float res = 0.0f;
        #pragma unroll
        for (int l = 0; l < 4; l++) {
            float s = wsum[0][l] + wsum[1][l] + wsum[2][l] + wsum[3][l];
            float nrm = sqrtf(s);
            res += v[l] * (a[l] / fmaxf(nrm, 1e-12f));
        }
        out[(size_t)r * EMB + t] = res;
    }
}

extern "C" void kernel_launch(void* const* d_in, const int* in_sizes, int n_in,
                              void* d_out, int out_size) {
    const int*   adj_row = (const int*)d_in[0];
    const int*   adj_col = (const int*)d_in[1];
    const float* adj_val = (const float*)d_in[2];
    const float* emb     = (const float*)d_in[3];
    const float* a       = (const float*)d_in[4];
    float*       out     = (float*)d_out;

    float* x1; cudaGetSymbolAddress((void**)&x1, g_x1);
    float* x2; cudaGetSymbolAddress((void**)&x2, g_x2);
    float* x3; cudaGetSymbolAddress((void**)&x3, g_x3);

    // CSR build
    zero_counts_kernel<<<(N_NODES + 255) / 256, 256>>>();
    hist_kernel<<<(N_EDGES + 255) / 256, 256>>>(adj_row);
    scan_kernel<<<1, 1024>>>();
    scatter_kernel<<<(N_EDGES + 255) / 256, 256>>>(adj_row);

    // 3 SpMM layers
    spmm_kernel<<<N_NODES, NTHREADS>>>(emb, x1, adj_col, adj_val);
    spmm_kernel<<<N_NODES, NTHREADS>>>(x1,  x2, adj_col, adj_val);
    spmm_kernel<<<N_NODES, NTHREADS>>>(x2,  x3, adj_col, adj_val);

    // normalize + weighted sum
    finalize_kernel<<<N_NODES, NTHREADS>>>(emb, a, out);
}

// round 2
// speedup vs baseline: 1.7870x; 1.7870x over previous
#include <cuda_runtime.h>
#include <math.h>

#define N_NODES 50000
#define N_EDGES 800000
#define EMB     100
#define NF4     25          // float4 per row
#define SCAN_B  256
#define SCAN_NB ((N_NODES + SCAN_B - 1) / SCAN_B)   // 196

// ---- static scratch (allocation-free rule: __device__ globals) ----
__device__ int   g_rowoff[N_NODES + 1];   // CSR row offsets
__device__ int   g_cursor[N_NODES];       // counts -> scatter cursors
__device__ int   g_bsum[SCAN_NB];         // per-block scan sums
__device__ int2  g_edges[N_EDGES];        // packed {col*EMB, val bits}, grouped by row
__device__ float g_x1[N_NODES * EMB];
__device__ float g_x2[N_NODES * EMB];
__device__ float g_x3[N_NODES * EMB];

// ---------------- CSR build ----------------
__global__ void zero_counts_kernel() {
    int i = blockIdx.x * blockDim.x + threadIdx.x;
    if (i < N_NODES) g_cursor[i] = 0;
}

__global__ void hist_kernel(const int* __restrict__ row) {
    int e = blockIdx.x * blockDim.x + threadIdx.x;
    if (e < N_EDGES) atomicAdd(&g_cursor[row[e]], 1);
}

// per-block inclusive scan of counts -> g_rowoff[i+1] (local), block sum -> g_bsum
__global__ void block_scan_kernel() {
    __shared__ int wsum[8];
    int i = blockIdx.x * SCAN_B + threadIdx.x;
    int lane = threadIdx.x & 31, warp = threadIdx.x >> 5;
    int v = (i < N_NODES) ? g_cursor[i] : 0;
    int x = v;
    #pragma unroll
    for (int off = 1; off < 32; off <<= 1) {
        int y = __shfl_up_sync(0xFFFFFFFFu, x, off);
        if (lane >= off) x += y;
    }
    if (lane == 31) wsum[warp] = x;
    __syncthreads();
    if (warp == 0) {
        int w = (lane < 8) ? wsum[lane] : 0;
        #pragma unroll
        for (int off = 1; off < 8; off <<= 1) {
            int y = __shfl_up_sync(0xFFFFFFFFu, w, off);
            if (lane >= off) w += y;
        }
        if (lane < 8) wsum[lane] = w;
    }
    __syncthreads();
    int incl = x + (warp > 0 ? wsum[warp - 1] : 0);
    if (i < N_NODES) g_rowoff[i + 1] = incl;
    if (threadIdx.x == SCAN_B - 1) g_bsum[blockIdx.x] = incl;
}

// single-block scan of the 196 block sums (exclusive, in place)
__global__ void bsum_scan_kernel() {
    __shared__ int wsum[8];
    int t = threadIdx.x;                 // 256 threads
    int lane = t & 31, warp = t >> 5;
    int v = (t < SCAN_NB) ? g_bsum[t] : 0;
    int x = v;
    #pragma unroll
    for (int off = 1; off < 32; off <<= 1) {
        int y = __shfl_up_sync(0xFFFFFFFFu, x, off);
        if (lane >= off) x += y;
    }
    if (lane == 31) wsum[warp] = x;
    __syncthreads();
    if (warp == 0) {
        int w = (lane < 8) ? wsum[lane] : 0;
        #pragma unroll
        for (int off = 1; off < 8; off <<= 1) {
            int y = __shfl_up_sync(0xFFFFFFFFu, w, off);
            if (lane >= off) w += y;
        }
        if (lane < 8) wsum[lane] = w;
    }
    __syncthreads();
    int excl = x - v + (warp > 0 ? wsum[warp - 1] : 0);
    if (t < SCAN_NB) g_bsum[t] = excl;
}

// add block offsets; produce final rowoff and cursors (counts still in g_cursor)
__global__ void fixup_kernel() {
    int i = blockIdx.x * SCAN_B + threadIdx.x;
    if (i < N_NODES) {
        int incl = g_rowoff[i + 1] + g_bsum[blockIdx.x];
        g_rowoff[i + 1] = incl;
        g_cursor[i] = incl - g_cursor[i];   // exclusive start = cursor
        if (i == 0) g_rowoff[0] = 0;
    }
}

__global__ void scatter_kernel(const int* __restrict__ row,
                               const int* __restrict__ col,
                               const float* __restrict__ val) {
    int e = blockIdx.x * blockDim.x + threadIdx.x;
    if (e < N_EDGES) {
        int pos = atomicAdd(&g_cursor[row[e]], 1);
        g_edges[pos] = make_int2(col[e] * EMB, __float_as_int(val[e]));
    }
}

// ---------------- SpMM: warp per row, float4 gathers ----------------
__global__ void __launch_bounds__(256) spmm_kernel(
    const float* __restrict__ x, float* __restrict__ y) {
    const int r = (blockIdx.x * blockDim.x + threadIdx.x) >> 5;
    if (r >= N_NODES) return;
    const int lane = threadIdx.x & 31;
    const int s = g_rowoff[r];
    const int e = g_rowoff[r + 1];

    float4 acc = make_float4(0.f, 0.f, 0.f, 0.f);
    for (int base = s; base < e; base += 32) {
        const int n = min(32, e - base);
        int2 ed = (base + lane < e) ? g_edges[base + lane] : make_int2(0, 0);
        for (int k = 0; k < n; k++) {
            const int   c = __shfl_sync(0xFFFFFFFFu, ed.x, k);
            const float v = __int_as_float(__shfl_sync(0xFFFFFFFFu, ed.y, k));
            if (lane < NF4) {
                float4 xv = __ldg((const float4*)(x + c) + lane);
                acc.x += v * xv.x;
                acc.y += v * xv.y;
                acc.z += v * xv.z;
                acc.w += v * xv.w;
            }
        }
    }
    if (lane < NF4)
        ((float4*)(y + (size_t)r * EMB))[lane] = acc;
}

// ---------------- finalize: out = sum_l a[l] * normalize(x_l) ----------------
__global__ void __launch_bounds__(128) finalize_kernel(
    const float* __restrict__ emb, const float* __restrict__ a,
    float* __restrict__ out) {
    const int r = blockIdx.x;
    const int t = threadIdx.x;

    float v[4];
    const float* x0 = emb  + (size_t)r * EMB;
    const float* x1 = g_x1 + (size_t)r * EMB;
    const float* x2 = g_x2 + (size_t)r * EMB;
    const float* x3 = g_x3 + (size_t)r * EMB;
    v[0] = (t < EMB) ? x0[t] : 0.0f;
    v[1] = (t < EMB) ? x1[t] : 0.0f;
    v[2] = (t < EMB) ? x2[t] : 0.0f;
    v[3] = (t < EMB) ? x3[t] : 0.0f;

    float sq[4];
    #pragma unroll
    for (int l = 0; l < 4; l++) sq[l] = v[l] * v[l];

    #pragma unroll
    for (int off = 16; off > 0; off >>= 1) {
        #pragma unroll
        for (int l = 0; l < 4; l++)
            sq[l] += __shfl_xor_sync(0xFFFFFFFFu, sq[l], off);
    }

    __shared__ float wsum[4][4];   // [warp][layer]
    const int warp = t >> 5, lane = t & 31;
    if (lane == 0) {
        #pragma unroll
        for (int l = 0; l < 4; l++) wsum[warp][l] = sq[l];
    }
    __syncthreads();

    if (t < EMB) {
        float res = 0.0f;
        #pragma unroll
        for (int l = 0; l < 4; l++) {
            float s = wsum[0][l] + wsum[1][l] + wsum[2][l] + wsum[3][l];
            float nrm = sqrtf(s);
            res += v[l] * (a[l] / fmaxf(nrm, 1e-12f));
        }
        out[(size_t)r * EMB + t] = res;
    }
}

extern "C" void kernel_launch(void* const* d_in, const int* in_sizes, int n_in,
                              void* d_out, int out_size) {
    const int*   adj_row = (const int*)d_in[0];
    const int*   adj_col = (const int*)d_in[1];
    const float* adj_val = (const float*)d_in[2];
    const float* emb     = (const float*)d_in[3];
    const float* a       = (const float*)d_in[4];
    float*       out     = (float*)d_out;

    float* x1; cudaGetSymbolAddress((void**)&x1, g_x1);
    float* x2; cudaGetSymbolAddress((void**)&x2, g_x2);
    float* x3; cudaGetSymbolAddress((void**)&x3, g_x3);

    // CSR build
    zero_counts_kernel<<<SCAN_NB, SCAN_B>>>();
    hist_kernel<<<(N_EDGES + 255) / 256, 256>>>(adj_row);
    block_scan_kernel<<<SCAN_NB, SCAN_B>>>();
    bsum_scan_kernel<<<1, SCAN_B>>>();
    fixup_kernel<<<SCAN_NB, SCAN_B>>>();
    scatter_kernel<<<(N_EDGES + 255) / 256, 256>>>(adj_row, adj_col, adj_val);

    // 3 SpMM layers (warp per row)
    const int SPMM_BLOCKS = (N_NODES * 32 + 255) / 256;
    spmm_kernel<<<SPMM_BLOCKS, 256>>>(emb, x1);
    spmm_kernel<<<SPMM_BLOCKS, 256>>>(x1,  x2);
    spmm_kernel<<<SPMM_BLOCKS, 256>>>(x2,  x3);

    // normalize + weighted sum
    finalize_kernel<<<N_NODES, 128>>>(emb, a, out);
}